// round 2
// baseline (speedup 1.0000x reference)
#include <cuda_runtime.h>
#include <cuda_bf16.h>

#define N_NODES 100000
#define N_EDGES 3200000
#define D 256
#define SCAN_B 1024
#define N_SCAN_BLOCKS ((N_NODES + SCAN_B - 1) / SCAN_B)   // 98

// ---------------- device scratch (static, allowed) ----------------
__device__ float g_support[(size_t)N_NODES * D];   // X @ W
__device__ int   g_cnt[N_NODES];
__device__ int   g_scan[N_NODES];
__device__ int   g_bsum[128];
__device__ int   g_row_ptr[N_NODES + 1];
__device__ int   g_cursor[N_NODES];
__device__ int   g_col[N_EDGES];
__device__ float g_val[N_EDGES];

// ---------------- 1) SGEMM: support = X @ W  (fp32, 128x128x8 tiles) ----------------
__global__ void sgemm_kernel(const float* __restrict__ A,   // [M,256]
                             const float* __restrict__ B)   // [256,256]
{
    const int M = N_NODES, N = D, K = D;
    __shared__ float As[8][128];
    __shared__ float Bs[8][128];

    int tid = threadIdx.x;                 // 256 threads
    int blockRow = blockIdx.y * 128;
    int blockCol = blockIdx.x * 128;

    int tr = tid / 16;                     // 0..15
    int tc = tid % 16;                     // 0..15

    float acc[8][8];
    #pragma unroll
    for (int i = 0; i < 8; i++)
        #pragma unroll
        for (int j = 0; j < 8; j++) acc[i][j] = 0.f;

    // A tile load mapping: 128x8 floats = 256 float4
    int aRow = tid / 2;
    int aCol = (tid % 2) * 4;
    // B tile load mapping: 8x128 floats = 256 float4
    int bRow = tid / 32;
    int bCol = (tid % 32) * 4;

    for (int k0 = 0; k0 < K; k0 += 8) {
        float4 av = make_float4(0.f, 0.f, 0.f, 0.f);
        int gr = blockRow + aRow;
        if (gr < M) av = *(const float4*)&A[(size_t)gr * K + k0 + aCol];
        As[aCol + 0][aRow] = av.x;
        As[aCol + 1][aRow] = av.y;
        As[aCol + 2][aRow] = av.z;
        As[aCol + 3][aRow] = av.w;

        float4 bv = *(const float4*)&B[(size_t)(k0 + bRow) * N + blockCol + bCol];
        *(float4*)&Bs[bRow][bCol] = bv;
        __syncthreads();

        #pragma unroll
        for (int kk = 0; kk < 8; kk++) {
            float ra[8], rb[8];
            #pragma unroll
            for (int i = 0; i < 8; i++) ra[i] = As[kk][tr * 8 + i];
            #pragma unroll
            for (int j = 0; j < 8; j++) rb[j] = Bs[kk][tc * 8 + j];
            #pragma unroll
            for (int i = 0; i < 8; i++)
                #pragma unroll
                for (int j = 0; j < 8; j++) acc[i][j] += ra[i] * rb[j];
        }
        __syncthreads();
    }

    #pragma unroll
    for (int i = 0; i < 8; i++) {
        int row = blockRow + tr * 8 + i;
        if (row >= M) continue;
        #pragma unroll
        for (int j = 0; j < 8; j += 4) {
            float4 v = make_float4(acc[i][j], acc[i][j+1], acc[i][j+2], acc[i][j+3]);
            *(float4*)&g_support[(size_t)row * N + blockCol + tc * 8 + j] = v;
        }
    }
}

// ---------------- 2) CSR build ----------------
__global__ void zero_cnt_kernel() {
    int i = blockIdx.x * blockDim.x + threadIdx.x;
    if (i < N_NODES) g_cnt[i] = 0;
}

__global__ void hist_kernel(const int* __restrict__ edge_row) {
    int e = blockIdx.x * blockDim.x + threadIdx.x;
    if (e < N_EDGES) atomicAdd(&g_cnt[edge_row[e]], 1);
}

// per-block inclusive scan over tiles of 1024
__global__ void scan_partial_kernel() {
    __shared__ int s[SCAN_B];
    int t = threadIdx.x;
    int i = blockIdx.x * SCAN_B + t;
    int v = (i < N_NODES) ? g_cnt[i] : 0;
    s[t] = v;
    __syncthreads();
    for (int off = 1; off < SCAN_B; off <<= 1) {
        int x = (t >= off) ? s[t - off] : 0;
        __syncthreads();
        s[t] += x;
        __syncthreads();
    }
    if (i < N_NODES) g_scan[i] = s[t];
    if (t == SCAN_B - 1) g_bsum[blockIdx.x] = s[t];
}

__global__ void scan_bsum_kernel() {   // <<<1,1>>> exclusive scan of 98 block sums
    int run = 0;
    for (int b = 0; b < N_SCAN_BLOCKS; b++) {
        int v = g_bsum[b];
        g_bsum[b] = run;
        run += v;
    }
}

__global__ void scan_finish_kernel() {
    int i = blockIdx.x * blockDim.x + threadIdx.x;
    if (i >= N_NODES) return;
    int rp = g_scan[i] + g_bsum[i >> 10];       // inclusive global prefix
    g_row_ptr[i + 1] = rp;
    g_cursor[i]      = rp - g_cnt[i];           // exclusive prefix = row start
    if (i == 0) g_row_ptr[0] = 0;
}

__global__ void scatter_kernel(const int* __restrict__ edge_row,
                               const int* __restrict__ edge_col,
                               const float* __restrict__ edge_val) {
    int e = blockIdx.x * blockDim.x + threadIdx.x;
    if (e >= N_EDGES) return;
    int r = edge_row[e];
    int p = atomicAdd(&g_cursor[r], 1);
    g_col[p] = edge_col[e];
    g_val[p] = edge_val[e];
}

// ---------------- 3) SpMM: warp per row, no output atomics ----------------
__global__ void spmm_kernel(const float* __restrict__ bias,
                            float* __restrict__ out) {
    int gwarp = (blockIdx.x * blockDim.x + threadIdx.x) >> 5;
    int lane  = threadIdx.x & 31;
    if (gwarp >= N_NODES) return;

    int beg = g_row_ptr[gwarp];
    int end = g_row_ptr[gwarp + 1];

    float4 a0 = make_float4(0.f, 0.f, 0.f, 0.f);   // dims [lane*4, lane*4+4)
    float4 a1 = make_float4(0.f, 0.f, 0.f, 0.f);   // dims [128+lane*4, ...)

    int e = beg;
    for (; e + 1 < end; e += 2) {
        int   c0 = g_col[e];
        float v0 = g_val[e];
        int   c1 = g_col[e + 1];
        float v1 = g_val[e + 1];
        const float4* p0 = (const float4*)&g_support[(size_t)c0 * D];
        const float4* p1 = (const float4*)&g_support[(size_t)c1 * D];
        float4 s00 = p0[lane];
        float4 s01 = p0[32 + lane];
        float4 s10 = p1[lane];
        float4 s11 = p1[32 + lane];
        a0.x += v0 * s00.x; a0.y += v0 * s00.y; a0.z += v0 * s00.z; a0.w += v0 * s00.w;
        a1.x += v0 * s01.x; a1.y += v0 * s01.y; a1.z += v0 * s01.z; a1.w += v0 * s01.w;
        a0.x += v1 * s10.x; a0.y += v1 * s10.y; a0.z += v1 * s10.z; a0.w += v1 * s10.w;
        a1.x += v1 * s11.x; a1.y += v1 * s11.y; a1.z += v1 * s11.z; a1.w += v1 * s11.w;
    }
    if (e < end) {
        int   c = g_col[e];
        float v = g_val[e];
        const float4* p = (const float4*)&g_support[(size_t)c * D];
        float4 s0 = p[lane];
        float4 s1 = p[32 + lane];
        a0.x += v * s0.x; a0.y += v * s0.y; a0.z += v * s0.z; a0.w += v * s0.w;
        a1.x += v * s1.x; a1.y += v * s1.y; a1.z += v * s1.z; a1.w += v * s1.w;
    }

    float4 b0 = ((const float4*)bias)[lane];
    float4 b1 = ((const float4*)bias)[32 + lane];
    a0.x += b0.x; a0.y += b0.y; a0.z += b0.z; a0.w += b0.w;
    a1.x += b1.x; a1.y += b1.y; a1.z += b1.z; a1.w += b1.w;

    float4* o = (float4*)&out[(size_t)gwarp * D];
    o[lane]      = a0;
    o[32 + lane] = a1;
}

// ---------------- launch ----------------
extern "C" void kernel_launch(void* const* d_in, const int* in_sizes, int n_in,
                              void* d_out, int out_size) {
    const float* input_feature = (const float*)d_in[0];   // [100000,256]
    const int*   edge_row      = (const int*)  d_in[1];   // [3.2M]
    const int*   edge_col      = (const int*)  d_in[2];   // [3.2M]
    const float* edge_val      = (const float*)d_in[3];   // [3.2M]
    const float* weight        = (const float*)d_in[4];   // [256,256]
    const float* bias          = (const float*)d_in[5];   // [256]
    float* out = (float*)d_out;

    // GEMM: support = X @ W
    dim3 ggrid(2, (N_NODES + 127) / 128);
    sgemm_kernel<<<ggrid, 256>>>(input_feature, weight);

    // CSR build
    zero_cnt_kernel<<<(N_NODES + 255) / 256, 256>>>();
    hist_kernel<<<(N_EDGES + 255) / 256, 256>>>(edge_row);
    scan_partial_kernel<<<N_SCAN_BLOCKS, SCAN_B>>>();
    scan_bsum_kernel<<<1, 1>>>();
    scan_finish_kernel<<<(N_NODES + 255) / 256, 256>>>();
    scatter_kernel<<<(N_EDGES + 255) / 256, 256>>>(edge_row, edge_col, edge_val);

    // SpMM + bias
    spmm_kernel<<<(N_NODES * 32 + 255) / 256, 256>>>(bias, out);
}

// round 5
// speedup vs baseline: 1.5526x; 1.5526x over previous
#include <cuda_runtime.h>
#include <cuda_bf16.h>
#include <cstdint>

#define N_NODES 100000
#define N_EDGES 3200000
#define D 256
#define SCAN_B 1024
#define N_SCAN_BLOCKS ((N_NODES + SCAN_B - 1) / SCAN_B)   // 98

// ---------------- device scratch (static, allowed) ----------------
__device__ float g_support[(size_t)N_NODES * D];   // X @ W
__device__ int   g_cnt[N_NODES];
__device__ int   g_scan[N_NODES];
__device__ int   g_bsum[128];
__device__ int   g_row_ptr[N_NODES + 1];
__device__ int   g_cursor[N_NODES];
__device__ int   g_col[N_EDGES];
__device__ float g_val[N_EDGES];

// ---------------- 1) GEMM: support = X @ W  (tf32 tensor cores) ----------------
// CTA tile 128x128x32, 8 warps as 4(m) x 2(n), warp tile 32x64.
// mma.sync.aligned.m16n8k8.row.col.f32.tf32.tf32.f32
#define BM 128
#define BN 128
#define BK 32
#define AS_STRIDE 36    // bank(m-frag load) = 4*group + tig = lane -> conflict-free
#define BS_STRIDE 136   // bank(n-frag load) = 8*tig + group    -> conflict-free

__device__ __forceinline__ uint32_t f2tf32(float f) {
    uint32_t o;
    asm("cvt.rna.tf32.f32 %0, %1;" : "=r"(o) : "f"(f));
    return o;
}

__global__ void __launch_bounds__(256, 2) gemm_tf32_kernel(const float* __restrict__ A,
                                                           const float* __restrict__ B) {
    __shared__ uint32_t As[BM * AS_STRIDE];
    __shared__ uint32_t Bs[BK * BS_STRIDE];

    const int tid  = threadIdx.x;
    const int warp = tid >> 5;
    const int lane = tid & 31;
    const int warp_m = (warp >> 1) * 32;   // 0,32,64,96
    const int warp_n = (warp & 1) * 64;    // 0,64
    const int group  = lane >> 2;          // 0..7
    const int tig    = lane & 3;           // 0..3

    const int blockRow = blockIdx.y * BM;
    const int blockCol = blockIdx.x * BN;

    float acc[2][8][4];
    #pragma unroll
    for (int mi = 0; mi < 2; mi++)
        #pragma unroll
        for (int ni = 0; ni < 8; ni++)
            #pragma unroll
            for (int c = 0; c < 4; c++) acc[mi][ni][c] = 0.f;

    for (int k0 = 0; k0 < D; k0 += BK) {
        // Load A tile: 128 rows x 32 cols = 1024 float4, 4 per thread
        #pragma unroll
        for (int i = 0; i < 4; i++) {
            int idx  = tid + i * 256;
            int row  = idx >> 3;
            int colv = (idx & 7) << 2;
            float4 v = make_float4(0.f, 0.f, 0.f, 0.f);
            int gr = blockRow + row;
            if (gr < N_NODES) v = *(const float4*)&A[(size_t)gr * D + k0 + colv];
            uint32_t* dst = &As[row * AS_STRIDE + colv];
            dst[0] = f2tf32(v.x); dst[1] = f2tf32(v.y);
            dst[2] = f2tf32(v.z); dst[3] = f2tf32(v.w);
        }
        // Load B tile: 32 rows x 128 cols = 1024 float4, 4 per thread
        #pragma unroll
        for (int i = 0; i < 4; i++) {
            int idx  = tid + i * 256;
            int row  = idx >> 5;
            int colv = (idx & 31) << 2;
            float4 v = *(const float4*)&B[(size_t)(k0 + row) * D + blockCol + colv];
            uint32_t* dst = &Bs[row * BS_STRIDE + colv];
            dst[0] = f2tf32(v.x); dst[1] = f2tf32(v.y);
            dst[2] = f2tf32(v.z); dst[3] = f2tf32(v.w);
        }
        __syncthreads();

        #pragma unroll
        for (int ks = 0; ks < 4; ks++) {
            const int kb = ks * 8;
            uint32_t af[2][4];
            #pragma unroll
            for (int mi = 0; mi < 2; mi++) {
                int m = warp_m + mi * 16 + group;
                af[mi][0] = As[(m    ) * AS_STRIDE + kb + tig    ];
                af[mi][1] = As[(m + 8) * AS_STRIDE + kb + tig    ];
                af[mi][2] = As[(m    ) * AS_STRIDE + kb + tig + 4];
                af[mi][3] = As[(m + 8) * AS_STRIDE + kb + tig + 4];
            }
            uint32_t bf[8][2];
            #pragma unroll
            for (int ni = 0; ni < 8; ni++) {
                int n = warp_n + ni * 8 + group;
                bf[ni][0] = Bs[(kb + tig    ) * BS_STRIDE + n];
                bf[ni][1] = Bs[(kb + tig + 4) * BS_STRIDE + n];
            }
            #pragma unroll
            for (int mi = 0; mi < 2; mi++)
                #pragma unroll
                for (int ni = 0; ni < 8; ni++) {
                    asm volatile(
                        "mma.sync.aligned.m16n8k8.row.col.f32.tf32.tf32.f32 "
                        "{%0,%1,%2,%3}, {%4,%5,%6,%7}, {%8,%9}, {%0,%1,%2,%3};\n"
                        : "+f"(acc[mi][ni][0]), "+f"(acc[mi][ni][1]),
                          "+f"(acc[mi][ni][2]), "+f"(acc[mi][ni][3])
                        : "r"(af[mi][0]), "r"(af[mi][1]), "r"(af[mi][2]), "r"(af[mi][3]),
                          "r"(bf[ni][0]), "r"(bf[ni][1]));
                }
        }
        __syncthreads();
    }

    // Store C: c0,c1 at (row, col), (row, col+1); c2,c3 at (row+8, ...)
    #pragma unroll
    for (int mi = 0; mi < 2; mi++) {
        int row0 = blockRow + warp_m + mi * 16 + group;
        #pragma unroll
        for (int ni = 0; ni < 8; ni++) {
            int col = blockCol + warp_n + ni * 8 + tig * 2;
            if (row0 < N_NODES)
                *(float2*)&g_support[(size_t)row0 * D + col] =
                    make_float2(acc[mi][ni][0], acc[mi][ni][1]);
            if (row0 + 8 < N_NODES)
                *(float2*)&g_support[(size_t)(row0 + 8) * D + col] =
                    make_float2(acc[mi][ni][2], acc[mi][ni][3]);
        }
    }
}

// ---------------- 2) CSR build ----------------
__global__ void zero_cnt_kernel() {
    int i = blockIdx.x * blockDim.x + threadIdx.x;
    if (i < N_NODES) g_cnt[i] = 0;
}

__global__ void hist_kernel(const int* __restrict__ edge_row) {
    int e = blockIdx.x * blockDim.x + threadIdx.x;
    if (e < N_EDGES) atomicAdd(&g_cnt[edge_row[e]], 1);
}

__global__ void scan_partial_kernel() {
    __shared__ int s[SCAN_B];
    int t = threadIdx.x;
    int i = blockIdx.x * SCAN_B + t;
    int v = (i < N_NODES) ? g_cnt[i] : 0;
    s[t] = v;
    __syncthreads();
    for (int off = 1; off < SCAN_B; off <<= 1) {
        int x = (t >= off) ? s[t - off] : 0;
        __syncthreads();
        s[t] += x;
        __syncthreads();
    }
    if (i < N_NODES) g_scan[i] = s[t];
    if (t == SCAN_B - 1) g_bsum[blockIdx.x] = s[t];
}

__global__ void scan_bsum_kernel() {   // <<<1,128>>> exclusive scan of 98 block sums
    __shared__ int s[128];
    int t = threadIdx.x;
    int v = (t < N_SCAN_BLOCKS) ? g_bsum[t] : 0;
    s[t] = v;
    __syncthreads();
    for (int off = 1; off < 128; off <<= 1) {
        int x = (t >= off) ? s[t - off] : 0;
        __syncthreads();
        s[t] += x;
        __syncthreads();
    }
    if (t < N_SCAN_BLOCKS) g_bsum[t] = s[t] - v;   // exclusive
}

__global__ void scan_finish_kernel() {
    int i = blockIdx.x * blockDim.x + threadIdx.x;
    if (i >= N_NODES) return;
    int rp = g_scan[i] + g_bsum[i >> 10];
    g_row_ptr[i + 1] = rp;
    g_cursor[i]      = rp - g_cnt[i];
    if (i == 0) g_row_ptr[0] = 0;
}

__global__ void scatter_kernel(const int* __restrict__ edge_row,
                               const int* __restrict__ edge_col,
                               const float* __restrict__ edge_val) {
    int e = blockIdx.x * blockDim.x + threadIdx.x;
    if (e >= N_EDGES) return;
    int r = edge_row[e];
    int p = atomicAdd(&g_cursor[r], 1);
    g_col[p] = edge_col[e];
    g_val[p] = edge_val[e];
}

// ---------------- 3) SpMM: warp per row, no output atomics ----------------
__global__ void spmm_kernel(const float* __restrict__ bias,
                            float* __restrict__ out) {
    int gwarp = (blockIdx.x * blockDim.x + threadIdx.x) >> 5;
    int lane  = threadIdx.x & 31;
    if (gwarp >= N_NODES) return;

    int beg = g_row_ptr[gwarp];
    int end = g_row_ptr[gwarp + 1];

    float4 a0 = make_float4(0.f, 0.f, 0.f, 0.f);
    float4 a1 = make_float4(0.f, 0.f, 0.f, 0.f);

    int e = beg;
    for (; e + 1 < end; e += 2) {
        int   c0 = g_col[e];
        float v0 = g_val[e];
        int   c1 = g_col[e + 1];
        float v1 = g_val[e + 1];
        const float4* p0 = (const float4*)&g_support[(size_t)c0 * D];
        const float4* p1 = (const float4*)&g_support[(size_t)c1 * D];
        float4 s00 = p0[lane];
        float4 s01 = p0[32 + lane];
        float4 s10 = p1[lane];
        float4 s11 = p1[32 + lane];
        a0.x += v0 * s00.x; a0.y += v0 * s00.y; a0.z += v0 * s00.z; a0.w += v0 * s00.w;
        a1.x += v0 * s01.x; a1.y += v0 * s01.y; a1.z += v0 * s01.z; a1.w += v0 * s01.w;
        a0.x += v1 * s10.x; a0.y += v1 * s10.y; a0.z += v1 * s10.z; a0.w += v1 * s10.w;
        a1.x += v1 * s11.x; a1.y += v1 * s11.y; a1.z += v1 * s11.z; a1.w += v1 * s11.w;
    }
    if (e < end) {
        int   c = g_col[e];
        float v = g_val[e];
        const float4* p = (const float4*)&g_support[(size_t)c * D];
        float4 s0 = p[lane];
        float4 s1 = p[32 + lane];
        a0.x += v * s0.x; a0.y += v * s0.y; a0.z += v * s0.z; a0.w += v * s0.w;
        a1.x += v * s1.x; a1.y += v * s1.y; a1.z += v * s1.z; a1.w += v * s1.w;
    }

    float4 b0 = ((const float4*)bias)[lane];
    float4 b1 = ((const float4*)bias)[32 + lane];
    a0.x += b0.x; a0.y += b0.y; a0.z += b0.z; a0.w += b0.w;
    a1.x += b1.x; a1.y += b1.y; a1.z += b1.z; a1.w += b1.w;

    float4* o = (float4*)&out[(size_t)gwarp * D];
    o[lane]      = a0;
    o[32 + lane] = a1;
}

// ---------------- launch ----------------
extern "C" void kernel_launch(void* const* d_in, const int* in_sizes, int n_in,
                              void* d_out, int out_size) {
    const float* input_feature = (const float*)d_in[0];   // [100000,256]
    const int*   edge_row      = (const int*)  d_in[1];   // [3.2M]
    const int*   edge_col      = (const int*)  d_in[2];   // [3.2M]
    const float* edge_val      = (const float*)d_in[3];   // [3.2M]
    const float* weight        = (const float*)d_in[4];   // [256,256]
    const float* bias          = (const float*)d_in[5];   // [256]
    float* out = (float*)d_out;

    // GEMM: support = X @ W (tf32 tensor cores). D/BN = 2 column blocks!
    gemm_tf32_kernel<<<dim3(D / BN, (N_NODES + BM - 1) / BM), 256>>>(input_feature, weight);

    // CSR build
    zero_cnt_kernel<<<(N_NODES + 255) / 256, 256>>>();
    hist_kernel<<<(N_EDGES + 255) / 256, 256>>>(edge_row);
    scan_partial_kernel<<<N_SCAN_BLOCKS, SCAN_B>>>();
    scan_bsum_kernel<<<1, 128>>>();
    scan_finish_kernel<<<(N_NODES + 255) / 256, 256>>>();
    scatter_kernel<<<(N_EDGES + 255) / 256, 256>>>(edge_row, edge_col, edge_val);

    // SpMM + bias
    spmm_kernel<<<(N_NODES * 32 + 255) / 256, 256>>>(bias, out);
}

// round 6
// speedup vs baseline: 2.0024x; 1.2897x over previous
#include <cuda_runtime.h>
#include <cuda_fp16.h>
#include <cstdint>

#define N_NODES 100000
#define N_EDGES 3200000
#define D 256
#define DH (D / 2)          // 128 half2 per row
#define SCAN_B 1024
#define N_SCAN_BLOCKS ((N_NODES + SCAN_B - 1) / SCAN_B)   // 98

// ---------------- device scratch (static, allowed) ----------------
__device__ __half2 g_support_h[(size_t)N_NODES * DH];   // X @ W in fp16 (51.2 MB)
__device__ int   g_cnt[N_NODES];
__device__ int   g_scan[N_NODES];
__device__ int   g_bsum[128];
__device__ int   g_row_ptr[N_NODES + 1];
__device__ int   g_cursor[N_NODES];
__device__ int   g_col[N_EDGES];
__device__ float g_val[N_EDGES];

// ---------------- 1) GEMM: support = X @ W  (tf32 tensor cores) ----------------
// CTA tile 128x128x32, 8 warps as 4(m) x 2(n), warp tile 32x64.
#define BM 128
#define BN 128
#define BK 32
#define AS_STRIDE 36    // bank(m-frag load) = 4*group + tig = lane -> conflict-free
#define BS_STRIDE 136   // bank(n-frag load) = 8*tig + group    -> conflict-free

__device__ __forceinline__ uint32_t f2tf32(float f) {
    uint32_t o;
    asm("cvt.rna.tf32.f32 %0, %1;" : "=r"(o) : "f"(f));
    return o;
}

__global__ void __launch_bounds__(256, 2) gemm_tf32_kernel(const float* __restrict__ A,
                                                           const float* __restrict__ B) {
    __shared__ uint32_t As[BM * AS_STRIDE];
    __shared__ uint32_t Bs[BK * BS_STRIDE];

    const int tid  = threadIdx.x;
    const int warp = tid >> 5;
    const int lane = tid & 31;
    const int warp_m = (warp >> 1) * 32;   // 0,32,64,96
    const int warp_n = (warp & 1) * 64;    // 0,64
    const int group  = lane >> 2;          // 0..7
    const int tig    = lane & 3;           // 0..3

    const int blockRow = blockIdx.y * BM;
    const int blockCol = blockIdx.x * BN;

    float acc[2][8][4];
    #pragma unroll
    for (int mi = 0; mi < 2; mi++)
        #pragma unroll
        for (int ni = 0; ni < 8; ni++)
            #pragma unroll
            for (int c = 0; c < 4; c++) acc[mi][ni][c] = 0.f;

    for (int k0 = 0; k0 < D; k0 += BK) {
        #pragma unroll
        for (int i = 0; i < 4; i++) {
            int idx  = tid + i * 256;
            int row  = idx >> 3;
            int colv = (idx & 7) << 2;
            float4 v = make_float4(0.f, 0.f, 0.f, 0.f);
            int gr = blockRow + row;
            if (gr < N_NODES) v = *(const float4*)&A[(size_t)gr * D + k0 + colv];
            uint32_t* dst = &As[row * AS_STRIDE + colv];
            dst[0] = f2tf32(v.x); dst[1] = f2tf32(v.y);
            dst[2] = f2tf32(v.z); dst[3] = f2tf32(v.w);
        }
        #pragma unroll
        for (int i = 0; i < 4; i++) {
            int idx  = tid + i * 256;
            int row  = idx >> 5;
            int colv = (idx & 31) << 2;
            float4 v = *(const float4*)&B[(size_t)(k0 + row) * D + blockCol + colv];
            uint32_t* dst = &Bs[row * BS_STRIDE + colv];
            dst[0] = f2tf32(v.x); dst[1] = f2tf32(v.y);
            dst[2] = f2tf32(v.z); dst[3] = f2tf32(v.w);
        }
        __syncthreads();

        #pragma unroll
        for (int ks = 0; ks < 4; ks++) {
            const int kb = ks * 8;
            uint32_t af[2][4];
            #pragma unroll
            for (int mi = 0; mi < 2; mi++) {
                int m = warp_m + mi * 16 + group;
                af[mi][0] = As[(m    ) * AS_STRIDE + kb + tig    ];
                af[mi][1] = As[(m + 8) * AS_STRIDE + kb + tig    ];
                af[mi][2] = As[(m    ) * AS_STRIDE + kb + tig + 4];
                af[mi][3] = As[(m + 8) * AS_STRIDE + kb + tig + 4];
            }
            uint32_t bf[8][2];
            #pragma unroll
            for (int ni = 0; ni < 8; ni++) {
                int n = warp_n + ni * 8 + group;
                bf[ni][0] = Bs[(kb + tig    ) * BS_STRIDE + n];
                bf[ni][1] = Bs[(kb + tig + 4) * BS_STRIDE + n];
            }
            #pragma unroll
            for (int mi = 0; mi < 2; mi++)
                #pragma unroll
                for (int ni = 0; ni < 8; ni++) {
                    asm volatile(
                        "mma.sync.aligned.m16n8k8.row.col.f32.tf32.tf32.f32 "
                        "{%0,%1,%2,%3}, {%4,%5,%6,%7}, {%8,%9}, {%0,%1,%2,%3};\n"
                        : "+f"(acc[mi][ni][0]), "+f"(acc[mi][ni][1]),
                          "+f"(acc[mi][ni][2]), "+f"(acc[mi][ni][3])
                        : "r"(af[mi][0]), "r"(af[mi][1]), "r"(af[mi][2]), "r"(af[mi][3]),
                          "r"(bf[ni][0]), "r"(bf[ni][1]));
                }
        }
        __syncthreads();
    }

    // Store C as fp16: c0,c1 are adjacent cols -> one half2 store each pair.
    #pragma unroll
    for (int mi = 0; mi < 2; mi++) {
        int row0 = blockRow + warp_m + mi * 16 + group;
        #pragma unroll
        for (int ni = 0; ni < 8; ni++) {
            int col = blockCol + warp_n + ni * 8 + tig * 2;   // even
            if (row0 < N_NODES)
                g_support_h[(size_t)row0 * DH + (col >> 1)] =
                    __floats2half2_rn(acc[mi][ni][0], acc[mi][ni][1]);
            if (row0 + 8 < N_NODES)
                g_support_h[(size_t)(row0 + 8) * DH + (col >> 1)] =
                    __floats2half2_rn(acc[mi][ni][2], acc[mi][ni][3]);
        }
    }
}

// ---------------- 2) CSR build ----------------
__global__ void zero_cnt_kernel() {
    int i = blockIdx.x * blockDim.x + threadIdx.x;
    if (i < N_NODES) g_cnt[i] = 0;
}

__global__ void hist_kernel(const int* __restrict__ edge_row) {
    int e = blockIdx.x * blockDim.x + threadIdx.x;
    if (e < N_EDGES) atomicAdd(&g_cnt[edge_row[e]], 1);
}

__global__ void scan_partial_kernel() {
    __shared__ int s[SCAN_B];
    int t = threadIdx.x;
    int i = blockIdx.x * SCAN_B + t;
    int v = (i < N_NODES) ? g_cnt[i] : 0;
    s[t] = v;
    __syncthreads();
    for (int off = 1; off < SCAN_B; off <<= 1) {
        int x = (t >= off) ? s[t - off] : 0;
        __syncthreads();
        s[t] += x;
        __syncthreads();
    }
    if (i < N_NODES) g_scan[i] = s[t];
    if (t == SCAN_B - 1) g_bsum[blockIdx.x] = s[t];
}

__global__ void scan_bsum_kernel() {   // <<<1,128>>> exclusive scan of 98 block sums
    __shared__ int s[128];
    int t = threadIdx.x;
    int v = (t < N_SCAN_BLOCKS) ? g_bsum[t] : 0;
    s[t] = v;
    __syncthreads();
    for (int off = 1; off < 128; off <<= 1) {
        int x = (t >= off) ? s[t - off] : 0;
        __syncthreads();
        s[t] += x;
        __syncthreads();
    }
    if (t < N_SCAN_BLOCKS) g_bsum[t] = s[t] - v;   // exclusive
}

__global__ void scan_finish_kernel() {
    int i = blockIdx.x * blockDim.x + threadIdx.x;
    if (i >= N_NODES) return;
    int rp = g_scan[i] + g_bsum[i >> 10];
    g_row_ptr[i + 1] = rp;
    g_cursor[i]      = rp - g_cnt[i];
    if (i == 0) g_row_ptr[0] = 0;
}

__global__ void scatter_kernel(const int* __restrict__ edge_row,
                               const int* __restrict__ edge_col,
                               const float* __restrict__ edge_val) {
    int e = blockIdx.x * blockDim.x + threadIdx.x;
    if (e >= N_EDGES) return;
    int r = edge_row[e];
    int p = atomicAdd(&g_cursor[r], 1);
    g_col[p] = edge_col[e];
    g_val[p] = edge_val[e];
}

// ---------------- 3) SpMM: warp per row, fp16 gather, fp32 accumulate ----------------
__device__ __forceinline__ void fma8(float* acc, uint4 q, float v) {
    const __half2* h = (const __half2*)&q;
    #pragma unroll
    for (int i = 0; i < 4; i++) {
        float2 f = __half22float2(h[i]);
        acc[2 * i]     += v * f.x;
        acc[2 * i + 1] += v * f.y;
    }
}

__global__ void spmm_kernel(const float* __restrict__ bias,
                            float* __restrict__ out) {
    int gwarp = (blockIdx.x * blockDim.x + threadIdx.x) >> 5;
    int lane  = threadIdx.x & 31;
    if (gwarp >= N_NODES) return;

    int beg = g_row_ptr[gwarp];
    int end = g_row_ptr[gwarp + 1];

    float acc[8];
    #pragma unroll
    for (int i = 0; i < 8; i++) acc[i] = 0.f;

    int e = beg;
    for (; e + 3 < end; e += 4) {
        int   c0 = g_col[e],     c1 = g_col[e + 1];
        int   c2 = g_col[e + 2], c3 = g_col[e + 3];
        float v0 = g_val[e],     v1 = g_val[e + 1];
        float v2 = g_val[e + 2], v3 = g_val[e + 3];
        uint4 q0 = ((const uint4*)&g_support_h[(size_t)c0 * DH])[lane];
        uint4 q1 = ((const uint4*)&g_support_h[(size_t)c1 * DH])[lane];
        uint4 q2 = ((const uint4*)&g_support_h[(size_t)c2 * DH])[lane];
        uint4 q3 = ((const uint4*)&g_support_h[(size_t)c3 * DH])[lane];
        fma8(acc, q0, v0);
        fma8(acc, q1, v1);
        fma8(acc, q2, v2);
        fma8(acc, q3, v3);
    }
    for (; e < end; e++) {
        int   c = g_col[e];
        float v = g_val[e];
        uint4 q = ((const uint4*)&g_support_h[(size_t)c * DH])[lane];
        fma8(acc, q, v);
    }

    // lane owns dims [lane*8, lane*8+8)
    const float4* bp = (const float4*)&bias[lane * 8];
    float4 b0 = bp[0], b1 = bp[1];
    acc[0] += b0.x; acc[1] += b0.y; acc[2] += b0.z; acc[3] += b0.w;
    acc[4] += b1.x; acc[5] += b1.y; acc[6] += b1.z; acc[7] += b1.w;

    float4* o = (float4*)&out[(size_t)gwarp * D + lane * 8];
    o[0] = make_float4(acc[0], acc[1], acc[2], acc[3]);
    o[1] = make_float4(acc[4], acc[5], acc[6], acc[7]);
}

// ---------------- launch ----------------
extern "C" void kernel_launch(void* const* d_in, const int* in_sizes, int n_in,
                              void* d_out, int out_size) {
    const float* input_feature = (const float*)d_in[0];   // [100000,256]
    const int*   edge_row      = (const int*)  d_in[1];   // [3.2M]
    const int*   edge_col      = (const int*)  d_in[2];   // [3.2M]
    const float* edge_val      = (const float*)d_in[3];   // [3.2M]
    const float* weight        = (const float*)d_in[4];   // [256,256]
    const float* bias          = (const float*)d_in[5];   // [256]
    float* out = (float*)d_out;

    // GEMM: support = X @ W (tf32 tensor cores), fp16 output
    gemm_tf32_kernel<<<dim3(D / BN, (N_NODES + BM - 1) / BM), 256>>>(input_feature, weight);

    // CSR build
    zero_cnt_kernel<<<(N_NODES + 255) / 256, 256>>>();
    hist_kernel<<<(N_EDGES + 255) / 256, 256>>>(edge_row);
    scan_partial_kernel<<<N_SCAN_BLOCKS, SCAN_B>>>();
    scan_bsum_kernel<<<1, 128>>>();
    scan_finish_kernel<<<(N_NODES + 255) / 256, 256>>>();
    scatter_kernel<<<(N_EDGES + 255) / 256, 256>>>(edge_row, edge_col, edge_val);

    // SpMM + bias
    spmm_kernel<<<(N_NODES * 32 + 255) / 256, 256>>>(bias, out);
}

// round 10
// speedup vs baseline: 2.1838x; 1.0906x over previous
#include <cuda_runtime.h>
#include <cuda_fp16.h>
#include <cstdint>

#define N_NODES 100000
#define N_EDGES 3200000
#define D 256
#define DH (D / 2)          // 128 half2 per row
#define SCAN_B 1024
#define N_SCAN_BLOCKS ((N_NODES + SCAN_B - 1) / SCAN_B)   // 98

// ---------------- device scratch (static, allowed) ----------------
__device__ __half2 g_support_h[(size_t)N_NODES * DH];   // X @ W in fp16 (51.2 MB)
__device__ int   g_cnt[N_NODES];
__device__ int   g_scan[N_NODES];
__device__ int   g_bsum[128];
__device__ int   g_row_ptr[N_NODES + 1];
__device__ int   g_cursor[N_NODES];
__device__ int2  g_edge[N_EDGES];    // packed (col, val-as-int)

// ---------------- 1) GEMM: support = X @ W  (tf32 tensor cores) ----------------
#define BM 128
#define BN 128
#define BK 32
#define AS_STRIDE 36
#define BS_STRIDE 136

__device__ __forceinline__ uint32_t f2tf32(float f) {
    uint32_t o;
    asm("cvt.rna.tf32.f32 %0, %1;" : "=r"(o) : "f"(f));
    return o;
}

__global__ void __launch_bounds__(256, 2) gemm_tf32_kernel(const float* __restrict__ A,
                                                           const float* __restrict__ B) {
    __shared__ uint32_t As[BM * AS_STRIDE];
    __shared__ uint32_t Bs[BK * BS_STRIDE];

    const int tid  = threadIdx.x;
    const int warp = tid >> 5;
    const int lane = tid & 31;
    const int warp_m = (warp >> 1) * 32;
    const int warp_n = (warp & 1) * 64;
    const int group  = lane >> 2;
    const int tig    = lane & 3;

    const int blockRow = blockIdx.y * BM;
    const int blockCol = blockIdx.x * BN;

    float acc[2][8][4];
    #pragma unroll
    for (int mi = 0; mi < 2; mi++)
        #pragma unroll
        for (int ni = 0; ni < 8; ni++)
            #pragma unroll
            for (int c = 0; c < 4; c++) acc[mi][ni][c] = 0.f;

    for (int k0 = 0; k0 < D; k0 += BK) {
        #pragma unroll
        for (int i = 0; i < 4; i++) {
            int idx  = tid + i * 256;
            int row  = idx >> 3;
            int colv = (idx & 7) << 2;
            float4 v = make_float4(0.f, 0.f, 0.f, 0.f);
            int gr = blockRow + row;
            if (gr < N_NODES) v = *(const float4*)&A[(size_t)gr * D + k0 + colv];
            uint32_t* dst = &As[row * AS_STRIDE + colv];
            dst[0] = f2tf32(v.x); dst[1] = f2tf32(v.y);
            dst[2] = f2tf32(v.z); dst[3] = f2tf32(v.w);
        }
        #pragma unroll
        for (int i = 0; i < 4; i++) {
            int idx  = tid + i * 256;
            int row  = idx >> 5;
            int colv = (idx & 31) << 2;
            float4 v = *(const float4*)&B[(size_t)(k0 + row) * D + blockCol + colv];
            uint32_t* dst = &Bs[row * BS_STRIDE + colv];
            dst[0] = f2tf32(v.x); dst[1] = f2tf32(v.y);
            dst[2] = f2tf32(v.z); dst[3] = f2tf32(v.w);
        }
        __syncthreads();

        #pragma unroll
        for (int ks = 0; ks < 4; ks++) {
            const int kb = ks * 8;
            uint32_t af[2][4];
            #pragma unroll
            for (int mi = 0; mi < 2; mi++) {
                int m = warp_m + mi * 16 + group;
                af[mi][0] = As[(m    ) * AS_STRIDE + kb + tig    ];
                af[mi][1] = As[(m + 8) * AS_STRIDE + kb + tig    ];
                af[mi][2] = As[(m    ) * AS_STRIDE + kb + tig + 4];
                af[mi][3] = As[(m + 8) * AS_STRIDE + kb + tig + 4];
            }
            uint32_t bf[8][2];
            #pragma unroll
            for (int ni = 0; ni < 8; ni++) {
                int n = warp_n + ni * 8 + group;
                bf[ni][0] = Bs[(kb + tig    ) * BS_STRIDE + n];
                bf[ni][1] = Bs[(kb + tig + 4) * BS_STRIDE + n];
            }
            #pragma unroll
            for (int mi = 0; mi < 2; mi++)
                #pragma unroll
                for (int ni = 0; ni < 8; ni++) {
                    asm volatile(
                        "mma.sync.aligned.m16n8k8.row.col.f32.tf32.tf32.f32 "
                        "{%0,%1,%2,%3}, {%4,%5,%6,%7}, {%8,%9}, {%0,%1,%2,%3};\n"
                        : "+f"(acc[mi][ni][0]), "+f"(acc[mi][ni][1]),
                          "+f"(acc[mi][ni][2]), "+f"(acc[mi][ni][3])
                        : "r"(af[mi][0]), "r"(af[mi][1]), "r"(af[mi][2]), "r"(af[mi][3]),
                          "r"(bf[ni][0]), "r"(bf[ni][1]));
                }
        }
        __syncthreads();
    }

    #pragma unroll
    for (int mi = 0; mi < 2; mi++) {
        int row0 = blockRow + warp_m + mi * 16 + group;
        #pragma unroll
        for (int ni = 0; ni < 8; ni++) {
            int col = blockCol + warp_n + ni * 8 + tig * 2;
            if (row0 < N_NODES)
                g_support_h[(size_t)row0 * DH + (col >> 1)] =
                    __floats2half2_rn(acc[mi][ni][0], acc[mi][ni][1]);
            if (row0 + 8 < N_NODES)
                g_support_h[(size_t)(row0 + 8) * DH + (col >> 1)] =
                    __floats2half2_rn(acc[mi][ni][2], acc[mi][ni][3]);
        }
    }
}

// ---------------- 2) CSR build ----------------
__global__ void hist_kernel(const int4* __restrict__ edge_row4) {
    int i = blockIdx.x * blockDim.x + threadIdx.x;
    if (i < N_EDGES / 4) {
        int4 r = edge_row4[i];
        atomicAdd(&g_cnt[r.x], 1);
        atomicAdd(&g_cnt[r.y], 1);
        atomicAdd(&g_cnt[r.z], 1);
        atomicAdd(&g_cnt[r.w], 1);
    }
}

__global__ void scan_partial_kernel() {
    __shared__ int s[SCAN_B];
    int t = threadIdx.x;
    int i = blockIdx.x * SCAN_B + t;
    int v = (i < N_NODES) ? g_cnt[i] : 0;
    s[t] = v;
    __syncthreads();
    for (int off = 1; off < SCAN_B; off <<= 1) {
        int x = (t >= off) ? s[t - off] : 0;
        __syncthreads();
        s[t] += x;
        __syncthreads();
    }
    if (i < N_NODES) g_scan[i] = s[t];
    if (t == SCAN_B - 1) g_bsum[blockIdx.x] = s[t];
}

__global__ void scan_bsum_kernel() {   // <<<1,128>>>
    __shared__ int s[128];
    int t = threadIdx.x;
    int v = (t < N_SCAN_BLOCKS) ? g_bsum[t] : 0;
    s[t] = v;
    __syncthreads();
    for (int off = 1; off < 128; off <<= 1) {
        int x = (t >= off) ? s[t - off] : 0;
        __syncthreads();
        s[t] += x;
        __syncthreads();
    }
    if (t < N_SCAN_BLOCKS) g_bsum[t] = s[t] - v;   // exclusive
}

__global__ void scan_finish_kernel() {
    int i = blockIdx.x * blockDim.x + threadIdx.x;
    if (i >= N_NODES) return;
    int rp = g_scan[i] + g_bsum[i >> 10];
    g_row_ptr[i + 1] = rp;
    g_cursor[i]      = rp - g_cnt[i];
    if (i == 0) g_row_ptr[0] = 0;
}

__global__ void scatter_kernel(const int4*   __restrict__ edge_row4,
                               const int4*   __restrict__ edge_col4,
                               const float4* __restrict__ edge_val4) {
    int i = blockIdx.x * blockDim.x + threadIdx.x;
    if (i >= N_EDGES / 4) return;
    int4   r = edge_row4[i];
    int4   c = edge_col4[i];
    float4 v = edge_val4[i];
    int p0 = atomicAdd(&g_cursor[r.x], 1);
    g_edge[p0] = make_int2(c.x, __float_as_int(v.x));
    int p1 = atomicAdd(&g_cursor[r.y], 1);
    g_edge[p1] = make_int2(c.y, __float_as_int(v.y));
    int p2 = atomicAdd(&g_cursor[r.z], 1);
    g_edge[p2] = make_int2(c.z, __float_as_int(v.z));
    int p3 = atomicAdd(&g_cursor[r.w], 1);
    g_edge[p3] = make_int2(c.w, __float_as_int(v.w));
}

// ---------------- 3) SpMM: warp per row, fp16 gather, fp32 accumulate ----------------
__device__ __forceinline__ void fma8(float* acc, uint4 q, float v) {
    const __half2* h = (const __half2*)&q;
    #pragma unroll
    for (int i = 0; i < 4; i++) {
        float2 f = __half22float2(h[i]);
        acc[2 * i]     += v * f.x;
        acc[2 * i + 1] += v * f.y;
    }
}

__global__ void spmm_kernel(const float* __restrict__ bias,
                            float* __restrict__ out) {
    int gwarp = (blockIdx.x * blockDim.x + threadIdx.x) >> 5;
    int lane  = threadIdx.x & 31;
    if (gwarp >= N_NODES) return;

    int beg = g_row_ptr[gwarp];
    int end = g_row_ptr[gwarp + 1];

    float acc[8];
    #pragma unroll
    for (int i = 0; i < 8; i++) acc[i] = 0.f;

    int e = beg;
    for (; e + 7 < end; e += 8) {
        int2 ed[8];
        #pragma unroll
        for (int j = 0; j < 8; j++) ed[j] = g_edge[e + j];
        uint4 q[8];
        #pragma unroll
        for (int j = 0; j < 8; j++)
            q[j] = ((const uint4*)&g_support_h[(size_t)ed[j].x * DH])[lane];
        #pragma unroll
        for (int j = 0; j < 8; j++)
            fma8(acc, q[j], __int_as_float(ed[j].y));
    }
    for (; e < end; e++) {
        int2 ed = g_edge[e];
        uint4 q = ((const uint4*)&g_support_h[(size_t)ed.x * DH])[lane];
        fma8(acc, q, __int_as_float(ed.y));
    }

    // lane owns dims [lane*8, lane*8+8)
    const float4* bp = (const float4*)&bias[lane * 8];
    float4 b0 = bp[0], b1 = bp[1];
    acc[0] += b0.x; acc[1] += b0.y; acc[2] += b0.z; acc[3] += b0.w;
    acc[4] += b1.x; acc[5] += b1.y; acc[6] += b1.z; acc[7] += b1.w;

    float4* o = (float4*)&out[(size_t)gwarp * D + lane * 8];
    o[0] = make_float4(acc[0], acc[1], acc[2], acc[3]);
    o[1] = make_float4(acc[4], acc[5], acc[6], acc[7]);
}

// ---------------- launch ----------------
extern "C" void kernel_launch(void* const* d_in, const int* in_sizes, int n_in,
                              void* d_out, int out_size) {
    const float* input_feature = (const float*)d_in[0];   // [100000,256]
    const int*   edge_row      = (const int*)  d_in[1];   // [3.2M]
    const int*   edge_col      = (const int*)  d_in[2];   // [3.2M]
    const float* edge_val      = (const float*)d_in[3];   // [3.2M]
    const float* weight        = (const float*)d_in[4];   // [256,256]
    const float* bias          = (const float*)d_in[5];   // [256]
    float* out = (float*)d_out;

    // GEMM: support = X @ W (tf32 tensor cores), fp16 output
    gemm_tf32_kernel<<<dim3(D / BN, (N_NODES + BM - 1) / BM), 256>>>(input_feature, weight);

    // CSR build
    void* cnt_ptr = nullptr;
    cudaGetSymbolAddress(&cnt_ptr, g_cnt);
    cudaMemsetAsync(cnt_ptr, 0, N_NODES * sizeof(int));
    hist_kernel<<<(N_EDGES / 4 + 255) / 256, 256>>>((const int4*)edge_row);
    scan_partial_kernel<<<N_SCAN_BLOCKS, SCAN_B>>>();
    scan_bsum_kernel<<<1, 128>>>();
    scan_finish_kernel<<<(N_NODES + 255) / 256, 256>>>();
    scatter_kernel<<<(N_EDGES / 4 + 255) / 256, 256>>>((const int4*)edge_row,
                                                       (const int4*)edge_col,
                                                       (const float4*)edge_val);

    // SpMM + bias
    spmm_kernel<<<(N_NODES * 32 + 255) / 256, 256>>>(bias, out);
}

// round 12
// speedup vs baseline: 2.3383x; 1.0707x over previous
#include <cuda_runtime.h>
#include <cuda_fp16.h>
#include <cstdint>

#define N_NODES 100000
#define N_EDGES 3200000
#define D 256
#define DH (D / 2)          // 128 half2 per row
#define SCAN_B 1024
#define N_SCAN_BLOCKS ((N_NODES + SCAN_B - 1) / SCAN_B)   // 98

#define AGG_READY 0x40000000
#define AGG_MASK  0x3FFFFFFF

// ---------------- device scratch (static, allowed) ----------------
__device__ __half2 g_support_h[(size_t)N_NODES * DH];   // X @ W in fp16 (51.2 MB)
// g_cnt and the scan aggregate flags share one symbol -> ONE memsetAsync clears both
__device__ int   g_cnt_agg[N_NODES + N_SCAN_BLOCKS];
#define G_CNT (g_cnt_agg)
#define G_AGG (g_cnt_agg + N_NODES)
__device__ int   g_row_ptr[N_NODES + 1];
__device__ int   g_cursor[N_NODES];
__device__ int2  g_edge[N_EDGES];    // packed (col, val-as-int)

// ---------------- 1) fused GEMM (tf32 tensor cores) + edge histogram ----------------
// GEMM: CTA tile 128x128x32, 8 warps as 4(m) x 2(n), warp tile 32x64.
#define BM 128
#define BN 128
#define BK 32
#define AS_STRIDE 36
#define BS_STRIDE 136

#define GEMM_BLOCKS 1564            // 2 x 782
#define HIST_BLOCKS 3128            // ceil(800000/256) padded to 2*GEMM_BLOCKS
#define FUSED_BLOCKS (GEMM_BLOCKS + HIST_BLOCKS)   // 4692, mapped 1:2 interleaved

__device__ __forceinline__ uint32_t f2tf32(float f) {
    uint32_t o;
    asm("cvt.rna.tf32.f32 %0, %1;" : "=r"(o) : "f"(f));
    return o;
}

__global__ void __launch_bounds__(256, 2) gemm_hist_kernel(const float* __restrict__ A,
                                                           const float* __restrict__ B,
                                                           const int4*  __restrict__ edge_row4) {
    __shared__ uint32_t As[BM * AS_STRIDE];
    __shared__ uint32_t Bs[BK * BS_STRIDE];

    const int tid = threadIdx.x;

    // interleaved mapping: every 3rd block is GEMM, other two are hist
    const int g3 = blockIdx.x / 3;
    const int r3 = blockIdx.x % 3;

    if (r3 != 0) {
        // ---- histogram branch ----
        int h = g3 * 2 + (r3 - 1);               // 0..3127
        int i = h * 256 + tid;
        if (i < N_EDGES / 4) {
            int4 r = edge_row4[i];
            atomicAdd(&G_CNT[r.x], 1);
            atomicAdd(&G_CNT[r.y], 1);
            atomicAdd(&G_CNT[r.z], 1);
            atomicAdd(&G_CNT[r.w], 1);
        }
        return;
    }

    // ---- GEMM branch: block id g3 in [0, 1564) ----
    const int warp = tid >> 5;
    const int lane = tid & 31;
    const int warp_m = (warp >> 1) * 32;
    const int warp_n = (warp & 1) * 64;
    const int group  = lane >> 2;
    const int tig    = lane & 3;

    const int blockRow = (g3 >> 1) * BM;
    const int blockCol = (g3 & 1) * BN;

    float acc[2][8][4];
    #pragma unroll
    for (int mi = 0; mi < 2; mi++)
        #pragma unroll
        for (int ni = 0; ni < 8; ni++)
            #pragma unroll
            for (int c = 0; c < 4; c++) acc[mi][ni][c] = 0.f;

    for (int k0 = 0; k0 < D; k0 += BK) {
        #pragma unroll
        for (int i = 0; i < 4; i++) {
            int idx  = tid + i * 256;
            int row  = idx >> 3;
            int colv = (idx & 7) << 2;
            float4 v = make_float4(0.f, 0.f, 0.f, 0.f);
            int gr = blockRow + row;
            if (gr < N_NODES) v = *(const float4*)&A[(size_t)gr * D + k0 + colv];
            uint32_t* dst = &As[row * AS_STRIDE + colv];
            dst[0] = f2tf32(v.x); dst[1] = f2tf32(v.y);
            dst[2] = f2tf32(v.z); dst[3] = f2tf32(v.w);
        }
        #pragma unroll
        for (int i = 0; i < 4; i++) {
            int idx  = tid + i * 256;
            int row  = idx >> 5;
            int colv = (idx & 31) << 2;
            float4 v = *(const float4*)&B[(size_t)(k0 + row) * D + blockCol + colv];
            uint32_t* dst = &Bs[row * BS_STRIDE + colv];
            dst[0] = f2tf32(v.x); dst[1] = f2tf32(v.y);
            dst[2] = f2tf32(v.z); dst[3] = f2tf32(v.w);
        }
        __syncthreads();

        #pragma unroll
        for (int ks = 0; ks < 4; ks++) {
            const int kb = ks * 8;
            uint32_t af[2][4];
            #pragma unroll
            for (int mi = 0; mi < 2; mi++) {
                int m = warp_m + mi * 16 + group;
                af[mi][0] = As[(m    ) * AS_STRIDE + kb + tig    ];
                af[mi][1] = As[(m + 8) * AS_STRIDE + kb + tig    ];
                af[mi][2] = As[(m    ) * AS_STRIDE + kb + tig + 4];
                af[mi][3] = As[(m + 8) * AS_STRIDE + kb + tig + 4];
            }
            uint32_t bf[8][2];
            #pragma unroll
            for (int ni = 0; ni < 8; ni++) {
                int n = warp_n + ni * 8 + group;
                bf[ni][0] = Bs[(kb + tig    ) * BS_STRIDE + n];
                bf[ni][1] = Bs[(kb + tig + 4) * BS_STRIDE + n];
            }
            #pragma unroll
            for (int mi = 0; mi < 2; mi++)
                #pragma unroll
                for (int ni = 0; ni < 8; ni++) {
                    asm volatile(
                        "mma.sync.aligned.m16n8k8.row.col.f32.tf32.tf32.f32 "
                        "{%0,%1,%2,%3}, {%4,%5,%6,%7}, {%8,%9}, {%0,%1,%2,%3};\n"
                        : "+f"(acc[mi][ni][0]), "+f"(acc[mi][ni][1]),
                          "+f"(acc[mi][ni][2]), "+f"(acc[mi][ni][3])
                        : "r"(af[mi][0]), "r"(af[mi][1]), "r"(af[mi][2]), "r"(af[mi][3]),
                          "r"(bf[ni][0]), "r"(bf[ni][1]));
                }
        }
        __syncthreads();
    }

    #pragma unroll
    for (int mi = 0; mi < 2; mi++) {
        int row0 = blockRow + warp_m + mi * 16 + group;
        #pragma unroll
        for (int ni = 0; ni < 8; ni++) {
            int col = blockCol + warp_n + ni * 8 + tig * 2;
            if (row0 < N_NODES)
                g_support_h[(size_t)row0 * DH + (col >> 1)] =
                    __floats2half2_rn(acc[mi][ni][0], acc[mi][ni][1]);
            if (row0 + 8 < N_NODES)
                g_support_h[(size_t)(row0 + 8) * DH + (col >> 1)] =
                    __floats2half2_rn(acc[mi][ni][2], acc[mi][ni][3]);
        }
    }
}

// ---------------- 2) single-kernel scan (decoupled aggregate lookback) ----------------
// 98 blocks <= 148 SMs -> guaranteed single wave, spin-wait is deadlock-free.
__global__ void scan_kernel() {
    __shared__ int s[SCAN_B];
    const int t = threadIdx.x;
    const int b = blockIdx.x;
    const int i = b * SCAN_B + t;

    int v = (i < N_NODES) ? G_CNT[i] : 0;
    s[t] = v;
    __syncthreads();
    for (int off = 1; off < SCAN_B; off <<= 1) {
        int x = (t >= off) ? s[t - off] : 0;
        __syncthreads();
        s[t] += x;
        __syncthreads();
    }
    int incl      = s[t];            // local inclusive prefix
    int aggregate = s[SCAN_B - 1];   // block total (valid for all threads)

    // publish aggregate (single atomic word carries value + ready bit)
    if (t == 0) atomicExch(&G_AGG[b], aggregate | AGG_READY);

    // lookback: thread t (< b) spins on predecessor t's aggregate
    int pred = 0;
    if (t < b) {
        int a;
        do { a = *(volatile int*)&G_AGG[t]; } while (!(a & AGG_READY));
        pred = a & AGG_MASK;
    }
    __syncthreads();          // s[] reuse barrier (incl/aggregate now in regs)
    s[t] = pred;
    __syncthreads();
    #pragma unroll
    for (int off = SCAN_B / 2; off > 0; off >>= 1) {
        if (t < off) s[t] += s[t + off];
        __syncthreads();
    }
    int prefix = s[0];        // sum of predecessor aggregates = exclusive block prefix

    if (i < N_NODES) {
        int gincl = prefix + incl;
        g_row_ptr[i + 1] = gincl;
        g_cursor[i]      = gincl - v;
        if (i == 0) g_row_ptr[0] = 0;
    }
}

// ---------------- 3) scatter ----------------
__global__ void scatter_kernel(const int4*   __restrict__ edge_row4,
                               const int4*   __restrict__ edge_col4,
                               const float4* __restrict__ edge_val4) {
    int i = blockIdx.x * blockDim.x + threadIdx.x;
    if (i >= N_EDGES / 4) return;
    int4   r = edge_row4[i];
    int4   c = edge_col4[i];
    float4 v = edge_val4[i];
    int p0 = atomicAdd(&g_cursor[r.x], 1);
    g_edge[p0] = make_int2(c.x, __float_as_int(v.x));
    int p1 = atomicAdd(&g_cursor[r.y], 1);
    g_edge[p1] = make_int2(c.y, __float_as_int(v.y));
    int p2 = atomicAdd(&g_cursor[r.z], 1);
    g_edge[p2] = make_int2(c.z, __float_as_int(v.z));
    int p3 = atomicAdd(&g_cursor[r.w], 1);
    g_edge[p3] = make_int2(c.w, __float_as_int(v.w));
}

// ---------------- 4) SpMM: warp per row, fp16 gather, fp32 accumulate ----------------
__device__ __forceinline__ void fma8(float* acc, uint4 q, float v) {
    const __half2* h = (const __half2*)&q;
    #pragma unroll
    for (int i = 0; i < 4; i++) {
        float2 f = __half22float2(h[i]);
        acc[2 * i]     += v * f.x;
        acc[2 * i + 1] += v * f.y;
    }
}

__global__ void spmm_kernel(const float* __restrict__ bias,
                            float* __restrict__ out) {
    int gwarp = (blockIdx.x * blockDim.x + threadIdx.x) >> 5;
    int lane  = threadIdx.x & 31;
    if (gwarp >= N_NODES) return;

    int beg = g_row_ptr[gwarp];
    int end = g_row_ptr[gwarp + 1];

    float acc[8];
    #pragma unroll
    for (int i = 0; i < 8; i++) acc[i] = 0.f;

    int e = beg;
    for (; e + 7 < end; e += 8) {
        int2 ed[8];
        #pragma unroll
        for (int j = 0; j < 8; j++) ed[j] = g_edge[e + j];
        uint4 q[8];
        #pragma unroll
        for (int j = 0; j < 8; j++)
            q[j] = ((const uint4*)&g_support_h[(size_t)ed[j].x * DH])[lane];
        #pragma unroll
        for (int j = 0; j < 8; j++)
            fma8(acc, q[j], __int_as_float(ed[j].y));
    }
    for (; e < end; e++) {
        int2 ed = g_edge[e];
        uint4 q = ((const uint4*)&g_support_h[(size_t)ed.x * DH])[lane];
        fma8(acc, q, __int_as_float(ed.y));
    }

    const float4* bp = (const float4*)&bias[lane * 8];
    float4 b0 = bp[0], b1 = bp[1];
    acc[0] += b0.x; acc[1] += b0.y; acc[2] += b0.z; acc[3] += b0.w;
    acc[4] += b1.x; acc[5] += b1.y; acc[6] += b1.z; acc[7] += b1.w;

    float4* o = (float4*)&out[(size_t)gwarp * D + lane * 8];
    o[0] = make_float4(acc[0], acc[1], acc[2], acc[3]);
    o[1] = make_float4(acc[4], acc[5], acc[6], acc[7]);
}

// ---------------- launch ----------------
extern "C" void kernel_launch(void* const* d_in, const int* in_sizes, int n_in,
                              void* d_out, int out_size) {
    const float* input_feature = (const float*)d_in[0];   // [100000,256]
    const int*   edge_row      = (const int*)  d_in[1];   // [3.2M]
    const int*   edge_col      = (const int*)  d_in[2];   // [3.2M]
    const float* edge_val      = (const float*)d_in[3];   // [3.2M]
    const float* weight        = (const float*)d_in[4];   // [256,256]
    const float* bias          = (const float*)d_in[5];   // [256]
    float* out = (float*)d_out;

    // clear counters + scan aggregate flags (one symbol, one memset)
    void* cnt_ptr = nullptr;
    cudaGetSymbolAddress(&cnt_ptr, g_cnt_agg);
    cudaMemsetAsync(cnt_ptr, 0, (N_NODES + N_SCAN_BLOCKS) * sizeof(int));

    // fused: tf32 GEMM (support = X @ W, fp16 out) + edge_row histogram
    gemm_hist_kernel<<<FUSED_BLOCKS, 256>>>(input_feature, weight, (const int4*)edge_row);

    // single-kernel scan -> row_ptr + cursor
    scan_kernel<<<N_SCAN_BLOCKS, SCAN_B>>>();

    // scatter edges into CSR
    scatter_kernel<<<(N_EDGES / 4 + 255) / 256, 256>>>((const int4*)edge_row,
                                                       (const int4*)edge_col,
                                                       (const float4*)edge_val);

    // SpMM + bias
    spmm_kernel<<<(N_NODES * 32 + 255) / 256, 256>>>(bias, out);
}